// round 8
// baseline (speedup 1.0000x reference)
#include <cuda_runtime.h>

// ---------------------------------------------------------------------------
// MS-Deformable-Attention, GB300 sm_103a.
// Shapes (compile-time): BATCH=2, LQ=LIN=21760, C=256, HEADS=8, LVLS=4, PTS=4,
// HEAD_DIM=32. Levels: (128,128),(64,64),(32,32),(16,16); starts 0,16384,20480,21504.
//
// Pipeline:
//   1) gemm: value    = input_flatten @ Wv   + bv   (43520x256)
//   2) gemm: off_raw  = query @ Woff + boff         (43520x256)
//   3) gemm: attn_raw = query @ Wa   + ba           (43520x128)
//   4) prep: softmax(16) + bilinear corner offsets/weights -> g_samp
//   5) gather: warp per (b,q,h), 16 samples x 4 corners -> g_attout
//   6) gemm: out = g_attout @ Wo + bo -> d_out
// ---------------------------------------------------------------------------

#define BATCHN 2
#define LQN    21760
#define LINN   21760
#define NROWS  (BATCHN * LQN)      // 43520
#define HEADS  8

// scratch (device globals: allocation-free per harness rules)
__device__ float g_value  [NROWS * 256];
__device__ float g_off    [NROWS * 256];
__device__ float g_attnraw[NROWS * 128];
__device__ float g_attout [NROWS * 256];

struct __align__(32) Samp { int4 o; float4 w; };
__device__ Samp g_samp[NROWS * HEADS * 16];   // 178 MB

// ---------------------------------------------------------------------------
// Packed f32x2 helpers (Blackwell FFMA2 path — 2x fp32 FMA throughput)
// ---------------------------------------------------------------------------
static __device__ __forceinline__ unsigned long long pk2(float x, float y) {
    unsigned long long r;
    asm("mov.b64 %0, {%1, %2};" : "=l"(r) : "f"(x), "f"(y));
    return r;
}
static __device__ __forceinline__ void fma2(unsigned long long& d,
                                            unsigned long long a,
                                            unsigned long long b) {
    asm("fma.rn.f32x2 %0, %1, %2, %3;" : "=l"(d) : "l"(a), "l"(b), "l"(d));
}

// ---------------------------------------------------------------------------
// GEMM: C[M,N] = A[M,256] @ W[256,N] + bias[N].  M % 128 == 0, N in {128,256}.
// Block 128x128, 256 threads, thread tile 8 rows x 8 cols, rows paired in f32x2.
// ---------------------------------------------------------------------------
#define BM 128
#define BN 128
#define BK 16
#define NKI 16   // 256 / BK

__global__ __launch_bounds__(256) void gemm_k256(
    const float* __restrict__ A, const float* __restrict__ W,
    const float* __restrict__ bias, float* __restrict__ C, int N)
{
    __shared__ float As[BK][BM];   // transposed: [k][m]
    __shared__ float Bs[BK][BN];   // [k][n]

    const int tid = threadIdx.x;
    const int tx  = tid & 15;      // n micro-tile
    const int ty  = tid >> 4;      // m micro-tile
    const int m0  = blockIdx.x * BM;
    const int n0  = blockIdx.y * BN;

    // A staging: each thread loads 8 contiguous k-floats of one row
    const int ar = tid >> 1;            // row 0..127
    const int kb = (tid & 1) * 8;       // k offset 0 or 8
    const float* Abase = A + (size_t)(m0 + ar) * 256 + kb;

    // B staging: each thread loads two float4s of the 16x128 tile
    const int f0  = 2 * tid;
    const int bk0 = f0 >> 5;                 // k row 0..15
    const int bc0 = (f0 & 31) * 4;
    const int bc1 = ((f0 + 1) & 31) * 4;
    const float* Bb0 = W + (size_t)bk0 * N + n0 + bc0;
    const float* Bb1 = W + (size_t)bk0 * N + n0 + bc1;

    float4 ra0, ra1, rb0, rb1;
    unsigned long long acc[4][8];
#pragma unroll
    for (int i = 0; i < 4; i++)
#pragma unroll
        for (int j = 0; j < 8; j++) acc[i][j] = 0ull;

#define FETCH(kt) do {                                              \
        ra0 = *(const float4*)(Abase + (kt) * BK);                  \
        ra1 = *(const float4*)(Abase + (kt) * BK + 4);              \
        rb0 = *(const float4*)(Bb0 + (size_t)(kt) * BK * N);        \
        rb1 = *(const float4*)(Bb1 + (size_t)(kt) * BK * N);        \
    } while (0)
#define STAGE() do {                                                           \
        As[kb+0][ar]=ra0.x; As[kb+1][ar]=ra0.y; As[kb+2][ar]=ra0.z; As[kb+3][ar]=ra0.w; \
        As[kb+4][ar]=ra1.x; As[kb+5][ar]=ra1.y; As[kb+6][ar]=ra1.z; As[kb+7][ar]=ra1.w; \
        *(float4*)&Bs[bk0][bc0] = rb0;                                         \
        *(float4*)&Bs[bk0][bc1] = rb1;                                         \
    } while (0)

    FETCH(0);
    STAGE();
    __syncthreads();

    for (int kt = 0; kt < NKI; kt++) {
        if (kt + 1 < NKI) FETCH(kt + 1);   // prefetch next tile into registers
#pragma unroll
        for (int kk = 0; kk < BK; kk++) {
            const ulonglong2 am0 = *(const ulonglong2*)&As[kk][ty * 8];     // rows 0,1 / 2,3
            const ulonglong2 am1 = *(const ulonglong2*)&As[kk][ty * 8 + 4]; // rows 4,5 / 6,7
            const float4 b0 = *(const float4*)&Bs[kk][tx * 8];
            const float4 b1 = *(const float4*)&Bs[kk][tx * 8 + 4];
            unsigned long long bd[8];
            bd[0]=pk2(b0.x,b0.x); bd[1]=pk2(b0.y,b0.y); bd[2]=pk2(b0.z,b0.z); bd[3]=pk2(b0.w,b0.w);
            bd[4]=pk2(b1.x,b1.x); bd[5]=pk2(b1.y,b1.y); bd[6]=pk2(b1.z,b1.z); bd[7]=pk2(b1.w,b1.w);
#pragma unroll
            for (int n = 0; n < 8; n++) {
                fma2(acc[0][n], am0.x, bd[n]);
                fma2(acc[1][n], am0.y, bd[n]);
                fma2(acc[2][n], am1.x, bd[n]);
                fma2(acc[3][n], am1.y, bd[n]);
            }
        }
        __syncthreads();
        if (kt + 1 < NKI) {
            STAGE();
            __syncthreads();
        }
    }
#undef FETCH
#undef STAGE

    float bv[8];
#pragma unroll
    for (int n = 0; n < 8; n++) bv[n] = bias[n0 + tx * 8 + n];

#pragma unroll
    for (int mp = 0; mp < 4; mp++) {
        float lo[8], hi[8];
#pragma unroll
        for (int n = 0; n < 8; n++) {
            union { unsigned long long u; float2 f; } cv;
            cv.u = acc[mp][n];
            lo[n] = cv.f.x + bv[n];
            hi[n] = cv.f.y + bv[n];
        }
        float* c0 = C + (size_t)(m0 + ty * 8 + 2 * mp) * N + n0 + tx * 8;
        float* c1 = c0 + N;
        *(float4*)(c0)     = make_float4(lo[0], lo[1], lo[2], lo[3]);
        *(float4*)(c0 + 4) = make_float4(lo[4], lo[5], lo[6], lo[7]);
        *(float4*)(c1)     = make_float4(hi[0], hi[1], hi[2], hi[3]);
        *(float4*)(c1 + 4) = make_float4(hi[4], hi[5], hi[6], hi[7]);
    }
}

// ---------------------------------------------------------------------------
// Prep: one thread per (b,q,h). Softmax over 16 logits; for each (l,p) compute
// pixel coords, bilinear corner weights (zero-padded OOB, indices clamped),
// fold attn weight in, emit {4 offsets into g_value, 4 weights}.
// ---------------------------------------------------------------------------
__global__ void prep_kernel(const float* __restrict__ attnraw,
                            const float* __restrict__ off,
                            const float* __restrict__ refp)
{
    const int idx = blockIdx.x * blockDim.x + threadIdx.x;
    if (idx >= NROWS * HEADS) return;
    const int h  = idx & 7;
    const int bq = idx >> 3;
    const int b  = bq / LQN;

    // softmax over the 16 (l,p) logits for this head
    float a[16];
    const float* ap = attnraw + (size_t)bq * 128 + h * 16;
    float mx = -1e30f;
#pragma unroll
    for (int j = 0; j < 16; j++) { a[j] = ap[j]; mx = fmaxf(mx, a[j]); }
    float s = 0.f;
#pragma unroll
    for (int j = 0; j < 16; j++) { a[j] = __expf(a[j] - mx); s += a[j]; }
    const float inv = 1.f / s;

    const float* op = off + (size_t)bq * 256 + h * 32;
    const float* rp = refp + (size_t)bq * 8;
    Samp* out = g_samp + (size_t)idx * 16;

    const int Hs[4] = {128, 64, 32, 16};
    const int Ws[4] = {128, 64, 32, 16};
    const int St[4] = {0, 16384, 20480, 21504};

#pragma unroll
    for (int l = 0; l < 4; l++) {
        const int Hl = Hs[l], Wl = Ws[l];
        const int rowbase = b * LINN + St[l];
        const float rx = rp[l * 2 + 0];
        const float ry = rp[l * 2 + 1];
#pragma unroll
        for (int p = 0; p < 4; p++) {
            const float ox = op[l * 8 + p * 2 + 0];
            const float oy = op[l * 8 + p * 2 + 1];
            // grid = 2*(ref+off)-1; x = (g+1)*0.5*W - 0.5 = (ref+off)*W - 0.5
            const float x = (rx + ox) * (float)Wl - 0.5f;
            const float y = (ry + oy) * (float)Hl - 0.5f;
            const float xf = floorf(x), yf = floorf(y);
            const float wx = x - xf, wy = y - yf;
            const int ix = (int)xf, iy = (int)yf;
            const float aw = a[l * 4 + p] * inv;

            const float w00 = (1.f - wx) * (1.f - wy) * aw;
            const float w10 = wx * (1.f - wy) * aw;
            const float w01 = (1.f - wx) * wy * aw;
            const float w11 = wx * wy * aw;

            const bool vx0 = (ix >= 0) && (ix < Wl);
            const bool vx1 = (ix + 1 >= 0) && (ix + 1 < Wl);
            const bool vy0 = (iy >= 0) && (iy < Hl);
            const bool vy1 = (iy + 1 >= 0) && (iy + 1 < Hl);

            const int x0c = min(max(ix, 0), Wl - 1);
            const int x1c = min(max(ix + 1, 0), Wl - 1);
            const int y0c = min(max(iy, 0), Hl - 1);
            const int y1c = min(max(iy + 1, 0), Hl - 1);

            Samp sm;
            const int hb = h << 5;
            sm.o.x = ((rowbase + y0c * Wl + x0c) << 8) + hb;
            sm.o.y = ((rowbase + y0c * Wl + x1c) << 8) + hb;
            sm.o.z = ((rowbase + y1c * Wl + x0c) << 8) + hb;
            sm.o.w = ((rowbase + y1c * Wl + x1c) << 8) + hb;
            sm.w.x = (vx0 && vy0) ? w00 : 0.f;
            sm.w.y = (vx1 && vy0) ? w10 : 0.f;
            sm.w.z = (vx0 && vy1) ? w01 : 0.f;
            sm.w.w = (vx1 && vy1) ? w11 : 0.f;
            out[l * 4 + p] = sm;
        }
    }
}

// ---------------------------------------------------------------------------
// Gather: block per (b,q), warp per head, lane per head-dim.
// acc_d = sum over 16 samples, 4 corners of w_c * value[off_c + d]
// ---------------------------------------------------------------------------
__global__ __launch_bounds__(256) void gather_kernel(float* __restrict__ outp)
{
    const int bq   = blockIdx.x;
    const int h    = threadIdx.x >> 5;
    const int lane = threadIdx.x & 31;
    const Samp* sp = g_samp + ((size_t)bq * 8 + h) * 16;

    float a0 = 0.f, a1 = 0.f, a2 = 0.f, a3 = 0.f;
#pragma unroll
    for (int s = 0; s < 16; s++) {
        const int4   o = sp[s].o;   // broadcast LDG.128
        const float4 w = sp[s].w;   // broadcast LDG.128
        a0 = fmaf(w.x, g_value[o.x + lane], a0);
        a1 = fmaf(w.y, g_value[o.y + lane], a1);
        a2 = fmaf(w.z, g_value[o.z + lane], a2);
        a3 = fmaf(w.w, g_value[o.w + lane], a3);
    }
    outp[(size_t)bq * 256 + threadIdx.x] = (a0 + a1) + (a2 + a3);
}

// ---------------------------------------------------------------------------
// kernel_launch — graph-capturable, allocation-free, deterministic.
// Input order per metadata: query, reference_points, input_flatten,
// input_spatial_shapes(i64, unused), input_level_start_index(i64, unused),
// Wv, bv, Woff, boff, Wa, ba, Wo, bo.
// ---------------------------------------------------------------------------
extern "C" void kernel_launch(void* const* d_in, const int* in_sizes, int n_in,
                              void* d_out, int out_size)
{
    const float* query = (const float*)d_in[0];
    const float* refp  = (const float*)d_in[1];
    const float* inpf  = (const float*)d_in[2];
    const float* Wv    = (const float*)d_in[5];
    const float* bv    = (const float*)d_in[6];
    const float* Woff  = (const float*)d_in[7];
    const float* boff  = (const float*)d_in[8];
    const float* Wa    = (const float*)d_in[9];
    const float* ba    = (const float*)d_in[10];
    const float* Wo    = (const float*)d_in[11];
    const float* bo    = (const float*)d_in[12];
    float* out = (float*)d_out;

    float *valp, *offp, *arawp, *aoutp;
    cudaGetSymbolAddress((void**)&valp,  g_value);
    cudaGetSymbolAddress((void**)&offp,  g_off);
    cudaGetSymbolAddress((void**)&arawp, g_attnraw);
    cudaGetSymbolAddress((void**)&aoutp, g_attout);

    dim3 blk(256);
    dim3 g2(NROWS / BM, 2);   // N = 256
    dim3 g1(NROWS / BM, 1);   // N = 128

    gemm_k256<<<g2, blk>>>(inpf,  Wv,   bv,   valp,  256);   // value
    gemm_k256<<<g2, blk>>>(query, Woff, boff, offp,  256);   // sampling offsets
    gemm_k256<<<g1, blk>>>(query, Wa,   ba,   arawp, 128);   // attn logits

    prep_kernel<<<(NROWS * HEADS) / 256, 256>>>(arawp, offp, refp);
    gather_kernel<<<NROWS, 256>>>(aoutp);

    gemm_k256<<<g2, blk>>>(aoutp, Wo, bo, out, 256);         // output proj
}

// round 10
// speedup vs baseline: 1.2171x; 1.2171x over previous
#include <cuda_runtime.h>
#include <cuda_fp16.h>

// ---------------------------------------------------------------------------
// MS-Deformable-Attention, GB300 sm_103a.
// BATCH=2, LQ=LIN=21760, C=256, HEADS=8, LVLS=4, PTS=4, HEAD_DIM=32.
// Levels: (128,128),(64,64),(32,32),(16,16); starts 0,16384,20480,21504.
//
// Pipeline (5 launches):
//   1) gemm(half out): value = input_flatten @ Wv + bv  -> g_valh (fp16)
//   2) gemm: off_raw  = query @ Woff + boff             -> g_off
//   3) gemm: attn_raw = query @ Wa   + ba               -> g_attnraw
//   4) fused prep+gather: softmax + bilinear in-warp (smem), half2 gather
//                                                       -> g_attout
//   5) gemm: out = g_attout @ Wo + bo                   -> d_out
// ---------------------------------------------------------------------------

#define BATCHN 2
#define LQN    21760
#define LINN   21760
#define NROWS  (BATCHN * LQN)      // 43520
#define HEADS  8

// scratch (device globals: allocation-free per harness rules)
__device__ __half g_valh  [NROWS * 256];   // value in fp16 (gather-only consumer)
__device__ float  g_off   [NROWS * 256];
__device__ float  g_attnraw[NROWS * 128];
__device__ float  g_attout[NROWS * 256];

// ---------------------------------------------------------------------------
// Packed f32x2 helpers (Blackwell FFMA2 path — 2x fp32 FMA throughput)
// ---------------------------------------------------------------------------
static __device__ __forceinline__ unsigned long long pk2(float x, float y) {
    unsigned long long r;
    asm("mov.b64 %0, {%1, %2};" : "=l"(r) : "f"(x), "f"(y));
    return r;
}
static __device__ __forceinline__ void fma2(unsigned long long& d,
                                            unsigned long long a,
                                            unsigned long long b) {
    asm("fma.rn.f32x2 %0, %1, %2, %3;" : "=l"(d) : "l"(a), "l"(b), "l"(d));
}

// ---------------------------------------------------------------------------
// GEMM: C[M,N] = A[M,256] @ W[256,N] + bias[N].  M % 128 == 0, N in {128,256}.
// Block 128x128, 256 threads, thread tile 8 rows x 8 cols, rows paired in f32x2.
// HALF_OUT: store fp16 (for the value GEMM feeding the gather).
// ---------------------------------------------------------------------------
#define BM 128
#define BN 128
#define BK 16
#define NKI 16   // 256 / BK

template <bool HALF_OUT>
__global__ __launch_bounds__(256) void gemm_k256(
    const float* __restrict__ A, const float* __restrict__ W,
    const float* __restrict__ bias, void* __restrict__ Cout, int N)
{
    __shared__ float As[BK][BM];   // transposed: [k][m]
    __shared__ float Bs[BK][BN];   // [k][n]

    const int tid = threadIdx.x;
    const int tx  = tid & 15;      // n micro-tile
    const int ty  = tid >> 4;      // m micro-tile
    const int m0  = blockIdx.x * BM;
    const int n0  = blockIdx.y * BN;

    // A staging: each thread loads 8 contiguous k-floats of one row
    const int ar = tid >> 1;            // row 0..127
    const int kb = (tid & 1) * 8;       // k offset 0 or 8
    const float* Abase = A + (size_t)(m0 + ar) * 256 + kb;

    // B staging: each thread loads two float4s of the 16x128 tile
    const int f0  = 2 * tid;
    const int bk0 = f0 >> 5;                 // k row 0..15
    const int bc0 = (f0 & 31) * 4;
    const int bc1 = ((f0 + 1) & 31) * 4;
    const float* Bb0 = W + (size_t)bk0 * N + n0 + bc0;
    const float* Bb1 = W + (size_t)bk0 * N + n0 + bc1;

    float4 ra0, ra1, rb0, rb1;
    unsigned long long acc[4][8];
#pragma unroll
    for (int i = 0; i < 4; i++)
#pragma unroll
        for (int j = 0; j < 8; j++) acc[i][j] = 0ull;

#define FETCH(kt) do {                                              \
        ra0 = *(const float4*)(Abase + (kt) * BK);                  \
        ra1 = *(const float4*)(Abase + (kt) * BK + 4);              \
        rb0 = *(const float4*)(Bb0 + (size_t)(kt) * BK * N);        \
        rb1 = *(const float4*)(Bb1 + (size_t)(kt) * BK * N);        \
    } while (0)
#define STAGE() do {                                                           \
        As[kb+0][ar]=ra0.x; As[kb+1][ar]=ra0.y; As[kb+2][ar]=ra0.z; As[kb+3][ar]=ra0.w; \
        As[kb+4][ar]=ra1.x; As[kb+5][ar]=ra1.y; As[kb+6][ar]=ra1.z; As[kb+7][ar]=ra1.w; \
        *(float4*)&Bs[bk0][bc0] = rb0;                                         \
        *(float4*)&Bs[bk0][bc1] = rb1;                                         \
    } while (0)

    FETCH(0);
    STAGE();
    __syncthreads();

    for (int kt = 0; kt < NKI; kt++) {
        if (kt + 1 < NKI) FETCH(kt + 1);   // prefetch next tile into registers
#pragma unroll
        for (int kk = 0; kk < BK; kk++) {
            const ulonglong2 am0 = *(const ulonglong2*)&As[kk][ty * 8];
            const ulonglong2 am1 = *(const ulonglong2*)&As[kk][ty * 8 + 4];
            const float4 b0 = *(const float4*)&Bs[kk][tx * 8];
            const float4 b1 = *(const float4*)&Bs[kk][tx * 8 + 4];
            unsigned long long bd[8];
            bd[0]=pk2(b0.x,b0.x); bd[1]=pk2(b0.y,b0.y); bd[2]=pk2(b0.z,b0.z); bd[3]=pk2(b0.w,b0.w);
            bd[4]=pk2(b1.x,b1.x); bd[5]=pk2(b1.y,b1.y); bd[6]=pk2(b1.z,b1.z); bd[7]=pk2(b1.w,b1.w);
#pragma unroll
            for (int n = 0; n < 8; n++) {
                fma2(acc[0][n], am0.x, bd[n]);
                fma2(acc[1][n], am0.y, bd[n]);
                fma2(acc[2][n], am1.x, bd[n]);
                fma2(acc[3][n], am1.y, bd[n]);
            }
        }
        __syncthreads();
        if (kt + 1 < NKI) {
            STAGE();
            __syncthreads();
        }
    }
#undef FETCH
#undef STAGE

    float bv[8];
#pragma unroll
    for (int n = 0; n < 8; n++) bv[n] = bias[n0 + tx * 8 + n];

#pragma unroll
    for (int mp = 0; mp < 4; mp++) {
        float lo[8], hi[8];
#pragma unroll
        for (int n = 0; n < 8; n++) {
            union { unsigned long long u; float2 f; } cv;
            cv.u = acc[mp][n];
            lo[n] = cv.f.x + bv[n];
            hi[n] = cv.f.y + bv[n];
        }
        const size_t r0 = (size_t)(m0 + ty * 8 + 2 * mp) * N + n0 + tx * 8;
        const size_t r1 = r0 + N;
        if (HALF_OUT) {
            __half* Ch = (__half*)Cout;
            union { uint4 u; __half2 h[4]; } p0, p1;
            p0.h[0] = __floats2half2_rn(lo[0], lo[1]);
            p0.h[1] = __floats2half2_rn(lo[2], lo[3]);
            p0.h[2] = __floats2half2_rn(lo[4], lo[5]);
            p0.h[3] = __floats2half2_rn(lo[6], lo[7]);
            p1.h[0] = __floats2half2_rn(hi[0], hi[1]);
            p1.h[1] = __floats2half2_rn(hi[2], hi[3]);
            p1.h[2] = __floats2half2_rn(hi[4], hi[5]);
            p1.h[3] = __floats2half2_rn(hi[6], hi[7]);
            *(uint4*)(Ch + r0) = p0.u;
            *(uint4*)(Ch + r1) = p1.u;
        } else {
            float* C = (float*)Cout;
            *(float4*)(C + r0)     = make_float4(lo[0], lo[1], lo[2], lo[3]);
            *(float4*)(C + r0 + 4) = make_float4(lo[4], lo[5], lo[6], lo[7]);
            *(float4*)(C + r1)     = make_float4(hi[0], hi[1], hi[2], hi[3]);
            *(float4*)(C + r1 + 4) = make_float4(hi[4], hi[5], hi[6], hi[7]);
        }
    }
}

// ---------------------------------------------------------------------------
// Fused prep+gather: block per (b,q), warp per head.
// Phase 1 (lanes 0..15, one lane per (l,p) sample): softmax over 16 logits
//   (width-16 shfl reductions), bilinear corner offsets (half-index into
//   g_valh) + attn-folded weights -> per-warp smem (private, __syncwarp only).
// Phase 2: 16 samples x 2 corner-pairs; lanes 0-15 = corner A, lanes 16-31 =
//   corner B; each lane loads one half2 (2 head-dims). Combine halves via
//   shfl_xor(16); lanes 0-15 store float2.
// ---------------------------------------------------------------------------
__global__ __launch_bounds__(256) void fused_gather(
    const float* __restrict__ attnraw, const float* __restrict__ off,
    const float* __restrict__ refp, float* __restrict__ outp)
{
    __shared__ int   s_o[HEADS][16][4];
    __shared__ float s_w[HEADS][16][4];

    const int bq   = blockIdx.x;
    const int h    = threadIdx.x >> 5;
    const int lane = threadIdx.x & 31;
    const int sm   = lane & 15;       // sample index (phase 1), half2 index (phase 2)
    const int b    = (bq >= LQN) ? 1 : 0;

    // ---- Phase 1: prep (all 32 lanes compute; lanes >=16 duplicate) ----
    {
        // softmax over the 16 (l,p) logits of this head
        float a = attnraw[(size_t)bq * 128 + h * 16 + sm];
        float mx = a;
#pragma unroll
        for (int i = 8; i > 0; i >>= 1)
            mx = fmaxf(mx, __shfl_xor_sync(0xffffffffu, mx, i, 16));
        float e = __expf(a - mx);
        float s = e;
#pragma unroll
        for (int i = 8; i > 0; i >>= 1)
            s += __shfl_xor_sync(0xffffffffu, s, i, 16);
        const float aw = e / s;

        const int l  = sm >> 2;              // level
        const int Wl = 128 >> l;             // = Hl
        const int St = (65536 - (65536 >> (2 * l))) / 3;  // 0,16384,20480,21504
        const int rowbase = b * LINN + St;

        const float rx = refp[(size_t)bq * 8 + l * 2 + 0];
        const float ry = refp[(size_t)bq * 8 + l * 2 + 1];
        const float ox = off[(size_t)bq * 256 + h * 32 + sm * 2 + 0];
        const float oy = off[(size_t)bq * 256 + h * 32 + sm * 2 + 1];

        // grid = 2*(ref+off)-1; pixel = (g+1)*0.5*W - 0.5 = (ref+off)*W - 0.5
        const float x = (rx + ox) * (float)Wl - 0.5f;
        const float y = (ry + oy) * (float)Wl - 0.5f;
        const float xf = floorf(x), yf = floorf(y);
        const float wx = x - xf, wy = y - yf;
        const int ix = (int)xf, iy = (int)yf;

        const float w00 = (1.f - wx) * (1.f - wy) * aw;
        const float w10 = wx * (1.f - wy) * aw;
        const float w01 = (1.f - wx) * wy * aw;
        const float w11 = wx * wy * aw;

        const bool vx0 = (ix >= 0) && (ix < Wl);
        const bool vx1 = (ix + 1 >= 0) && (ix + 1 < Wl);
        const bool vy0 = (iy >= 0) && (iy < Wl);
        const bool vy1 = (iy + 1 >= 0) && (iy + 1 < Wl);

        const int x0c = min(max(ix, 0), Wl - 1);
        const int x1c = min(max(ix + 1, 0), Wl - 1);
        const int y0c = min(max(iy, 0), Wl - 1);
        const int y1c = min(max(iy + 1, 0), Wl - 1);

        if (lane < 16) {
            const int hb = h << 5;   // half-index offset of this head within a row
            s_o[h][sm][0] = ((rowbase + y0c * Wl + x0c) << 8) + hb;
            s_o[h][sm][1] = ((rowbase + y0c * Wl + x1c) << 8) + hb;
            s_o[h][sm][2] = ((rowbase + y1c * Wl + x0c) << 8) + hb;
            s_o[h][sm][3] = ((rowbase + y1c * Wl + x1c) << 8) + hb;
            s_w[h][sm][0] = (vx0 && vy0) ? w00 : 0.f;
            s_w[h][sm][1] = (vx1 && vy0) ? w10 : 0.f;
            s_w[h][sm][2] = (vx0 && vy1) ? w01 : 0.f;
            s_w[h][sm][3] = (vx1 && vy1) ? w11 : 0.f;
        }
    }
    __syncwarp();   // smem slice [h] is private to this warp

    // ---- Phase 2: gather (half2 loads, 2 corners per iteration) ----
    const int sub = lane >> 4;     // which corner of the pair this half-warp owns
    float ax = 0.f, ay = 0.f;
#pragma unroll
    for (int s = 0; s < 16; s++) {
#pragma unroll
        for (int p = 0; p < 2; p++) {
            const int   c = p * 2 + sub;
            const int   o = s_o[h][s][c];
            const float w = s_w[h][s][c];
            const __half2 v = *(const __half2*)(g_valh + o + 2 * sm);
            const float2 f = __half22float2(v);
            ax = fmaf(w, f.x, ax);
            ay = fmaf(w, f.y, ay);
        }
    }
    ax += __shfl_xor_sync(0xffffffffu, ax, 16);
    ay += __shfl_xor_sync(0xffffffffu, ay, 16);
    if (lane < 16)
        *(float2*)(outp + (size_t)bq * 256 + h * 32 + 2 * sm) = make_float2(ax, ay);
}

// ---------------------------------------------------------------------------
// kernel_launch — graph-capturable, allocation-free, deterministic.
// Inputs: query, reference_points, input_flatten, spatial_shapes(i64, unused),
// level_start_index(i64, unused), Wv, bv, Woff, boff, Wa, ba, Wo, bo.
// ---------------------------------------------------------------------------
extern "C" void kernel_launch(void* const* d_in, const int* in_sizes, int n_in,
                              void* d_out, int out_size)
{
    const float* query = (const float*)d_in[0];
    const float* refp  = (const float*)d_in[1];
    const float* inpf  = (const float*)d_in[2];
    const float* Wv    = (const float*)d_in[5];
    const float* bv    = (const float*)d_in[6];
    const float* Woff  = (const float*)d_in[7];
    const float* boff  = (const float*)d_in[8];
    const float* Wa    = (const float*)d_in[9];
    const float* ba    = (const float*)d_in[10];
    const float* Wo    = (const float*)d_in[11];
    const float* bo    = (const float*)d_in[12];
    float* out = (float*)d_out;

    void *valp, *offp, *arawp, *aoutp;
    cudaGetSymbolAddress(&valp,  g_valh);
    cudaGetSymbolAddress(&offp,  g_off);
    cudaGetSymbolAddress(&arawp, g_attnraw);
    cudaGetSymbolAddress(&aoutp, g_attout);

    dim3 blk(256);
    dim3 g2(NROWS / BM, 2);   // N = 256
    dim3 g1(NROWS / BM, 1);   // N = 128

    gemm_k256<true ><<<g2, blk>>>(inpf,  Wv,   bv,   valp,  256);  // value (fp16 out)
    gemm_k256<false><<<g2, blk>>>(query, Woff, boff, offp,  256);  // sampling offsets
    gemm_k256<false><<<g1, blk>>>(query, Wa,   ba,   arawp, 128);  // attn logits

    fused_gather<<<NROWS, blk>>>((const float*)arawp, (const float*)offp,
                                 refp, (float*)aoutp);

    gemm_k256<false><<<g2, blk>>>((const float*)aoutp, Wo, bo, out, 256);  // out proj
}

// round 12
// speedup vs baseline: 1.9255x; 1.5820x over previous
#include <cuda_runtime.h>
#include <cuda_fp16.h>
#include <cstdint>

// ---------------------------------------------------------------------------
// MS-Deformable-Attention, GB300 sm_103a.
// BATCH=2, LQ=LIN=21760, C=256, HEADS=8, LVLS=4, PTS=4, HEAD_DIM=32.
// Levels: (128,128),(64,64),(32,32),(16,16); starts 0,16384,20480,21504.
//
// Pipeline (5 launches):
//   1) hmma gemm (split-fp16, half out): value = inpf @ Wv + bv -> g_valh
//   2) hmma gemm (split-fp16):           off   = query @ Woff + boff
//   3) hmma gemm (plain fp16):           attn  = query @ Wa + ba
//   4) fused prep+gather (softmax + bilinear in-warp, half2 gather)
//   5) hmma gemm (split-fp16):           out   = attout @ Wo + bo
// ---------------------------------------------------------------------------

#define BATCHN 2
#define LQN    21760
#define LINN   21760
#define NROWS  (BATCHN * LQN)      // 43520
#define HEADS  8

__device__ __half g_valh  [NROWS * 256];   // value, fp16 (gather-only consumer)
__device__ float  g_off   [NROWS * 256];
__device__ float  g_attnraw[NROWS * 128];
__device__ float  g_attout[NROWS * 256];

// ---------------------------------------------------------------------------
// mma.sync helpers
// ---------------------------------------------------------------------------
static __device__ __forceinline__ uint32_t sptr(const void* p) {
    return (uint32_t)__cvta_generic_to_shared(p);
}
static __device__ __forceinline__ void ldsm4(uint32_t* r, uint32_t a) {
    asm volatile("ldmatrix.sync.aligned.m8n8.x4.shared.b16 {%0,%1,%2,%3}, [%4];"
                 : "=r"(r[0]), "=r"(r[1]), "=r"(r[2]), "=r"(r[3]) : "r"(a));
}
static __device__ __forceinline__ void ldsm4t(uint32_t* r, uint32_t a) {
    asm volatile("ldmatrix.sync.aligned.m8n8.x4.trans.shared.b16 {%0,%1,%2,%3}, [%4];"
                 : "=r"(r[0]), "=r"(r[1]), "=r"(r[2]), "=r"(r[3]) : "r"(a));
}
static __device__ __forceinline__ void mma16816(float* d, const uint32_t* a,
                                                const uint32_t* b) {
    asm volatile(
        "mma.sync.aligned.m16n8k16.row.col.f32.f16.f16.f32 "
        "{%0,%1,%2,%3}, {%4,%5,%6,%7}, {%8,%9}, {%0,%1,%2,%3};"
        : "+f"(d[0]), "+f"(d[1]), "+f"(d[2]), "+f"(d[3])
        : "r"(a[0]), "r"(a[1]), "r"(a[2]), "r"(a[3]), "r"(b[0]), "r"(b[1]));
}

// pack 8 floats -> 8 halves (hi) and, for SPLIT, the fp16 residual (lo)
static __device__ __forceinline__ void cvt8(const float4& x, const float4& y,
                                            uint4& hi) {
    union { uint4 q; __half2 h[4]; } r;
    r.h[0] = __floats2half2_rn(x.x, x.y);
    r.h[1] = __floats2half2_rn(x.z, x.w);
    r.h[2] = __floats2half2_rn(y.x, y.y);
    r.h[3] = __floats2half2_rn(y.z, y.w);
    hi = r.q;
}
static __device__ __forceinline__ void split8(const float4& x, const float4& y,
                                              uint4& hi, uint4& lo) {
    float f[8] = {x.x, x.y, x.z, x.w, y.x, y.y, y.z, y.w};
    union { uint4 q; __half h[8]; } H, L;
#pragma unroll
    for (int i = 0; i < 8; i++) {
        __half h = __float2half_rn(f[i]);
        H.h[i] = h;
        L.h[i] = __float2half_rn(f[i] - __half2float(h));
    }
    hi = H.q; lo = L.q;
}

// ---------------------------------------------------------------------------
// HMMA GEMM: C[M,N] = A[M,256] @ W[256,N] + bias.  M%128==0, N in {128,256}.
// Block 128x128, 8 warps (4 m-warps x 2 n-warps), warp tile 32x64.
// K chunks of 16, double-buffered smem. A smem stride 24 halves (pad), W 136.
// SPLIT: A=hi+lo, W=hi+lo, 3 mma passes -> fp32-class accuracy.
// ---------------------------------------------------------------------------
#define AST 24    // A smem row stride (halves): 16 k + 8 pad, ldsm conflict-free
#define WST 136   // W smem row stride (halves): 128 n + 8 pad

template <bool SPLIT, bool HALF_OUT>
__global__ __launch_bounds__(256) void gemm_hmma(
    const float* __restrict__ A, const float* __restrict__ W,
    const float* __restrict__ bias, void* __restrict__ Cout, int N)
{
    __shared__ __half sAh[2][128 * AST];
    __shared__ __half sWh[2][16 * WST];
    __shared__ __half sAl[SPLIT ? 2 : 1][128 * AST];
    __shared__ __half sWl[SPLIT ? 2 : 1][16 * WST];

    const int tid = threadIdx.x;
    const int m0  = blockIdx.x * 128;
    const int n0  = blockIdx.y * 128;

    // staging assignments (8 floats per thread per tensor per chunk)
    const int ar  = tid >> 1;            // A row 0..127
    const int akq = (tid & 1) * 8;       // A k sub-offset
    const float* Ag = A + (size_t)(m0 + ar) * 256 + akq;
    const int aoff = ar * AST + akq;

    const int wr  = tid >> 4;            // W k row 0..15
    const int wnq = (tid & 15) * 8;      // W n sub-offset
    const float* Wg = W + (size_t)wr * N + n0 + wnq;
    const int woff = wr * WST + wnq;

    // compute-side ids
    const int lane = tid & 31;
    const int wid  = tid >> 5;
    const int wm   = wid & 3;            // m warp -> rows wm*32
    const int wn   = wid >> 2;           // n warp -> cols wn*64
    const int lrow = lane & 15;
    const int lcol = (lane >> 4) << 3;   // halves

    float acc[2][8][4];
#pragma unroll
    for (int mt = 0; mt < 2; mt++)
#pragma unroll
        for (int j = 0; j < 8; j++)
#pragma unroll
            for (int v = 0; v < 4; v++) acc[mt][j][v] = 0.f;

    float4 af0, af1, wf0, wf1;

#define GLOAD(kc) do {                                                  \
        af0 = *(const float4*)(Ag + (kc) * 16);                         \
        af1 = *(const float4*)(Ag + (kc) * 16 + 4);                     \
        const float* wp = Wg + (size_t)(kc) * 16 * N;                   \
        wf0 = *(const float4*)wp;                                       \
        wf1 = *(const float4*)(wp + 4);                                 \
    } while (0)

#define GSTORE(buf) do {                                                \
        if (SPLIT) {                                                    \
            uint4 h, l;                                                 \
            split8(af0, af1, h, l);                                     \
            *(uint4*)&sAh[buf][aoff] = h;                               \
            *(uint4*)&sAl[buf][aoff] = l;                               \
            split8(wf0, wf1, h, l);                                     \
            *(uint4*)&sWh[buf][woff] = h;                               \
            *(uint4*)&sWl[buf][woff] = l;                               \
        } else {                                                        \
            uint4 h;                                                    \
            cvt8(af0, af1, h);  *(uint4*)&sAh[buf][aoff] = h;           \
            cvt8(wf0, wf1, h);  *(uint4*)&sWh[buf][woff] = h;           \
        }                                                               \
    } while (0)

    GLOAD(0);
    GSTORE(0);
    __syncthreads();

    for (int kc = 0; kc < 16; kc++) {
        if (kc < 15) GLOAD(kc + 1);
        const int buf = kc & 1;

        const uint32_t aAddr0 =
            sptr(&sAh[buf][(wm * 32 + lrow) * AST + lcol]);
        const uint32_t bAddr0 =
            sptr(&sWh[buf][lrow * WST + wn * 64 + lcol]);

        uint32_t ah[2][4], bh[4][4];
#pragma unroll
        for (int mt = 0; mt < 2; mt++)
            ldsm4(ah[mt], aAddr0 + mt * (16 * AST * 2));
#pragma unroll
        for (int nb = 0; nb < 4; nb++)
            ldsm4t(bh[nb], bAddr0 + nb * 32);       // 16 halves = 32 B

#pragma unroll
        for (int mt = 0; mt < 2; mt++)
#pragma unroll
            for (int j = 0; j < 8; j++)
                mma16816(acc[mt][j], ah[mt], &bh[j >> 1][(j & 1) * 2]);

        if (SPLIT) {
            const uint32_t aAddrL =
                sptr(&sAl[buf][(wm * 32 + lrow) * AST + lcol]);
            const uint32_t bAddrL =
                sptr(&sWl[buf][lrow * WST + wn * 64 + lcol]);
            uint32_t al[2][4], bl[4][4];
#pragma unroll
            for (int mt = 0; mt < 2; mt++)
                ldsm4(al[mt], aAddrL + mt * (16 * AST * 2));
#pragma unroll
            for (int nb = 0; nb < 4; nb++)
                ldsm4t(bl[nb], bAddrL + nb * 32);

#pragma unroll
            for (int mt = 0; mt < 2; mt++)
#pragma unroll
                for (int j = 0; j < 8; j++) {
                    mma16816(acc[mt][j], ah[mt], &bl[j >> 1][(j & 1) * 2]);
                    mma16816(acc[mt][j], al[mt], &bh[j >> 1][(j & 1) * 2]);
                }
        }

        if (kc < 15) {
            GSTORE((kc + 1) & 1);
            __syncthreads();
        }
    }
#undef GLOAD
#undef GSTORE

    // epilogue
#pragma unroll
    for (int mt = 0; mt < 2; mt++) {
        const int r0 = m0 + wm * 32 + mt * 16 + (lane >> 2);
#pragma unroll
        for (int j = 0; j < 8; j++) {
            const int c0 = n0 + wn * 64 + j * 8 + (lane & 3) * 2;
            const float2 bb = *(const float2*)&bias[c0];
            const float d0 = acc[mt][j][0] + bb.x;
            const float d1 = acc[mt][j][1] + bb.y;
            const float d2 = acc[mt][j][2] + bb.x;
            const float d3 = acc[mt][j][3] + bb.y;
            if (HALF_OUT) {
                __half* C = (__half*)Cout;
                *(__half2*)(C + (size_t)r0 * N + c0)       = __floats2half2_rn(d0, d1);
                *(__half2*)(C + (size_t)(r0 + 8) * N + c0) = __floats2half2_rn(d2, d3);
            } else {
                float* C = (float*)Cout;
                *(float2*)(C + (size_t)r0 * N + c0)       = make_float2(d0, d1);
                *(float2*)(C + (size_t)(r0 + 8) * N + c0) = make_float2(d2, d3);
            }
        }
    }
}

// ---------------------------------------------------------------------------
// Fused prep+gather: block per (b,q), warp per head.
// Phase 1 (per (l,p) lane): softmax(16) via width-16 shfl + bilinear corner
//   offsets/weights -> per-warp smem.  Phase 2: 16 samples x 2 corner pairs,
//   lanes 0-15 corner A / 16-31 corner B, half2 loads; combine via shfl(16).
// ---------------------------------------------------------------------------
__global__ __launch_bounds__(256) void fused_gather(
    const float* __restrict__ attnraw, const float* __restrict__ off,
    const float* __restrict__ refp, float* __restrict__ outp)
{
    __shared__ int   s_o[HEADS][16][4];
    __shared__ float s_w[HEADS][16][4];

    const int bq   = blockIdx.x;
    const int h    = threadIdx.x >> 5;
    const int lane = threadIdx.x & 31;
    const int sm   = lane & 15;
    const int b    = (bq >= LQN) ? 1 : 0;

    {
        float a = attnraw[(size_t)bq * 128 + h * 16 + sm];
        float mx = a;
#pragma unroll
        for (int i = 8; i > 0; i >>= 1)
            mx = fmaxf(mx, __shfl_xor_sync(0xffffffffu, mx, i, 16));
        float e = __expf(a - mx);
        float s = e;
#pragma unroll
        for (int i = 8; i > 0; i >>= 1)
            s += __shfl_xor_sync(0xffffffffu, s, i, 16);
        const float aw = e / s;

        const int l  = sm >> 2;
        const int Wl = 128 >> l;
        const int St = (65536 - (65536 >> (2 * l))) / 3;  // 0,16384,20480,21504
        const int rowbase = b * LINN + St;

        const float rx = refp[(size_t)bq * 8 + l * 2 + 0];
        const float ry = refp[(size_t)bq * 8 + l * 2 + 1];
        const float ox = off[(size_t)bq * 256 + h * 32 + sm * 2 + 0];
        const float oy = off[(size_t)bq * 256 + h * 32 + sm * 2 + 1];

        const float x = (rx + ox) * (float)Wl - 0.5f;
        const float y = (ry + oy) * (float)Wl - 0.5f;
        const float xf = floorf(x), yf = floorf(y);
        const float wx = x - xf, wy = y - yf;
        const int ix = (int)xf, iy = (int)yf;

        const float w00 = (1.f - wx) * (1.f - wy) * aw;
        const float w10 = wx * (1.f - wy) * aw;
        const float w01 = (1.f - wx) * wy * aw;
        const float w11 = wx * wy * aw;

        const bool vx0 = (ix >= 0) && (ix < Wl);
        const bool vx1 = (ix + 1 >= 0) && (ix + 1 < Wl);
        const bool vy0 = (iy >= 0) && (iy < Wl);
        const bool vy1 = (iy + 1 >= 0) && (iy + 1 < Wl);

        const int x0c = min(max(ix, 0), Wl - 1);
        const int x1c = min(max(ix + 1, 0), Wl - 1);
        const int y0c = min(max(iy, 0), Wl - 1);
        const int y1c = min(max(iy + 1, 0), Wl - 1);

        if (lane < 16) {
            const int hb = h << 5;
            s_o[h][sm][0] = ((rowbase + y0c * Wl + x0c) << 8) + hb;
            s_o[h][sm][1] = ((rowbase + y0c * Wl + x1c) << 8) + hb;
            s_o[h][sm][2] = ((rowbase + y1c * Wl + x0c) << 8) + hb;
            s_o[h][sm][3] = ((rowbase + y1c * Wl + x1c) << 8) + hb;
            s_w[h][sm][0] = (vx0 && vy0) ? w00 : 0.f;
            s_w[h][sm][1] = (vx1 && vy0) ? w10 : 0.f;
            s_w[h][sm][2] = (vx0 && vy1) ? w01 : 0.f;
            s_w[h][sm][3] = (vx1 && vy1) ? w11 : 0.f;
        }
    }
    __syncwarp();

    const int sub = lane >> 4;
    float ax = 0.f, ay = 0.f;
#pragma unroll
    for (int s = 0; s < 16; s++) {
#pragma unroll
        for (int p = 0; p < 2; p++) {
            const int   c = p * 2 + sub;
            const int   o = s_o[h][s][c];
            const float w = s_w[h][s][c];
            const __half2 v = *(const __half2*)(g_valh + o + 2 * sm);
            const float2 f = __half22float2(v);
            ax = fmaf(w, f.x, ax);
            ay = fmaf(w, f.y, ay);
        }
    }
    ax += __shfl_xor_sync(0xffffffffu, ax, 16);
    ay += __shfl_xor_sync(0xffffffffu, ay, 16);
    if (lane < 16)
        *(float2*)(outp + (size_t)bq * 256 + h * 32 + 2 * sm) = make_float2(ax, ay);
}

// ---------------------------------------------------------------------------
// kernel_launch — graph-capturable, allocation-free, deterministic.
// Inputs: query, reference_points, input_flatten, spatial_shapes(i64, unused),
// level_start_index(i64, unused), Wv, bv, Woff, boff, Wa, ba, Wo, bo.
// ---------------------------------------------------------------------------
extern "C" void kernel_launch(void* const* d_in, const int* in_sizes, int n_in,
                              void* d_out, int out_size)
{
    const float* query = (const float*)d_in[0];
    const float* refp  = (const float*)d_in[1];
    const float* inpf  = (const float*)d_in[2];
    const float* Wv    = (const float*)d_in[5];
    const float* bv    = (const float*)d_in[6];
    const float* Woff  = (const float*)d_in[7];
    const float* boff  = (const float*)d_in[8];
    const float* Wa    = (const float*)d_in[9];
    const float* ba    = (const float*)d_in[10];
    const float* Wo    = (const float*)d_in[11];
    const float* bo    = (const float*)d_in[12];
    float* out = (float*)d_out;

    void *valp, *offp, *arawp, *aoutp;
    cudaGetSymbolAddress(&valp,  g_valh);
    cudaGetSymbolAddress(&offp,  g_off);
    cudaGetSymbolAddress(&arawp, g_attnraw);
    cudaGetSymbolAddress(&aoutp, g_attout);

    dim3 blk(256);
    dim3 g2(NROWS / 128, 2);   // N = 256
    dim3 g1(NROWS / 128, 1);   // N = 128

    // value (split-fp16, fp16 out)
    gemm_hmma<true,  true ><<<g2, blk>>>(inpf,  Wv,   bv,   valp,  256);
    // sampling offsets (split-fp16 — coordinate-sensitive)
    gemm_hmma<true,  false><<<g2, blk>>>(query, Woff, boff, offp,  256);
    // attn logits (plain fp16 — softmax-insensitive)
    gemm_hmma<false, false><<<g1, blk>>>(query, Wa,   ba,   arawp, 128);

    fused_gather<<<NROWS, blk>>>((const float*)arawp, (const float*)offp,
                                 refp, (float*)aoutp);

    // output projection (split-fp16)
    gemm_hmma<true,  false><<<g2, blk>>>((const float*)aoutp, Wo, bo, out, 256);
}

// round 17
// speedup vs baseline: 2.0740x; 1.0771x over previous
#include <cuda_runtime.h>
#include <cuda_fp16.h>
#include <cstdint>

// ---------------------------------------------------------------------------
// MS-Deformable-Attention, GB300 sm_103a.
// BATCH=2, LQ=LIN=21760, C=256, HEADS=8, LVLS=4, PTS=4, HEAD_DIM=32.
// Levels: (128,128),(64,64),(32,32),(16,16); starts 0,16384,20480,21504.
//
// Pipeline (5 launches) — R12-proven base; gather phase-2 restructured:
//   1) hmma gemm (split-fp16, half out): value = inpf @ Wv + bv -> g_valh
//   2) hmma gemm (split-fp16):           off   = query @ Woff + boff
//   3) hmma gemm (plain fp16):           attn  = query @ Wa + ba
//   4) fused prep+gather: 4-corner lane split, LDG.64 per sample per lane
//   5) hmma gemm (split-fp16):           out   = attout @ Wo + bo
// ---------------------------------------------------------------------------

#define BATCHN 2
#define LQN    21760
#define LINN   21760
#define NROWS  (BATCHN * LQN)      // 43520
#define HEADS  8

__device__ __half g_valh  [NROWS * 256];   // value, fp16, row-major
__device__ float  g_off   [NROWS * 256];
__device__ float  g_attnraw[NROWS * 128];
__device__ float  g_attout[NROWS * 256];

// ---------------------------------------------------------------------------
// mma.sync helpers
// ---------------------------------------------------------------------------
static __device__ __forceinline__ uint32_t sptr(const void* p) {
    return (uint32_t)__cvta_generic_to_shared(p);
}
static __device__ __forceinline__ void ldsm4(uint32_t* r, uint32_t a) {
    asm volatile("ldmatrix.sync.aligned.m8n8.x4.shared.b16 {%0,%1,%2,%3}, [%4];"
                 : "=r"(r[0]), "=r"(r[1]), "=r"(r[2]), "=r"(r[3]) : "r"(a));
}
static __device__ __forceinline__ void ldsm4t(uint32_t* r, uint32_t a) {
    asm volatile("ldmatrix.sync.aligned.m8n8.x4.trans.shared.b16 {%0,%1,%2,%3}, [%4];"
                 : "=r"(r[0]), "=r"(r[1]), "=r"(r[2]), "=r"(r[3]) : "r"(a));
}
static __device__ __forceinline__ void mma16816(float* d, const uint32_t* a,
                                                const uint32_t* b) {
    asm volatile(
        "mma.sync.aligned.m16n8k16.row.col.f32.f16.f16.f32 "
        "{%0,%1,%2,%3}, {%4,%5,%6,%7}, {%8,%9}, {%0,%1,%2,%3};"
        : "+f"(d[0]), "+f"(d[1]), "+f"(d[2]), "+f"(d[3])
        : "r"(a[0]), "r"(a[1]), "r"(a[2]), "r"(a[3]), "r"(b[0]), "r"(b[1]));
}

static __device__ __forceinline__ void cvt8(const float4& x, const float4& y,
                                            uint4& hi) {
    union { uint4 q; __half2 h[4]; } r;
    r.h[0] = __floats2half2_rn(x.x, x.y);
    r.h[1] = __floats2half2_rn(x.z, x.w);
    r.h[2] = __floats2half2_rn(y.x, y.y);
    r.h[3] = __floats2half2_rn(y.z, y.w);
    hi = r.q;
}
static __device__ __forceinline__ void split8(const float4& x, const float4& y,
                                              uint4& hi, uint4& lo) {
    float f[8] = {x.x, x.y, x.z, x.w, y.x, y.y, y.z, y.w};
    union { uint4 q; __half h[8]; } H, L;
#pragma unroll
    for (int i = 0; i < 8; i++) {
        __half h = __float2half_rn(f[i]);
        H.h[i] = h;
        L.h[i] = __float2half_rn(f[i] - __half2float(h));
    }
    hi = H.q; lo = L.q;
}

// ---------------------------------------------------------------------------
// HMMA GEMM (byte-identical to the R12-passing version):
// C[M,N] = A[M,256] @ W[256,N] + bias.  M%128==0, N in {128,256}.
// Block 128x128, 8 warps (4 m x 2 n), warp tile 32x64, K chunks of 16,
// double-buffered smem.  SPLIT: 3-pass hi/lo -> fp32-class accuracy.
// HALF_OUT: store fp16 row-major into Cout.
// ---------------------------------------------------------------------------
#define AST 24
#define WST 136

template <bool SPLIT, bool HALF_OUT>
__global__ __launch_bounds__(256) void gemm_hmma(
    const float* __restrict__ A, const float* __restrict__ W,
    const float* __restrict__ bias, void* __restrict__ Cout, int N)
{
    __shared__ __half sAh[2][128 * AST];
    __shared__ __half sWh[2][16 * WST];
    __shared__ __half sAl[SPLIT ? 2 : 1][128 * AST];
    __shared__ __half sWl[SPLIT ? 2 : 1][16 * WST];

    const int tid = threadIdx.x;
    const int m0  = blockIdx.x * 128;
    const int n0  = blockIdx.y * 128;

    const int ar  = tid >> 1;
    const int akq = (tid & 1) * 8;
    const float* Ag = A + (size_t)(m0 + ar) * 256 + akq;
    const int aoff = ar * AST + akq;

    const int wr  = tid >> 4;
    const int wnq = (tid & 15) * 8;
    const float* Wg = W + (size_t)wr * N + n0 + wnq;
    const int woff = wr * WST + wnq;

    const int lane = tid & 31;
    const int wid  = tid >> 5;
    const int wm   = wid & 3;
    const int wn   = wid >> 2;
    const int lrow = lane & 15;
    const int lcol = (lane >> 4) << 3;

    float acc[2][8][4];
#pragma unroll
    for (int mt = 0; mt < 2; mt++)
#pragma unroll
        for (int j = 0; j < 8; j++)
#pragma unroll
            for (int v = 0; v < 4; v++) acc[mt][j][v] = 0.f;

    float4 af0, af1, wf0, wf1;

#define GLOAD(kc) do {                                                  \
        af0 = *(const float4*)(Ag + (kc) * 16);                         \
        af1 = *(const float4*)(Ag + (kc) * 16 + 4);                     \
        const float* wp = Wg + (size_t)(kc) * 16 * N;                   \
        wf0 = *(const float4*)wp;                                       \
        wf1 = *(const float4*)(wp + 4);                                 \
    } while (0)

#define GSTORE(buf) do {                                                \
        if (SPLIT) {                                                    \
            uint4 h, l;                                                 \
            split8(af0, af1, h, l);                                     \
            *(uint4*)&sAh[buf][aoff] = h;                               \
            *(uint4*)&sAl[buf][aoff] = l;                               \
            split8(wf0, wf1, h, l);                                     \
            *(uint4*)&sWh[buf][woff] = h;                               \
            *(uint4*)&sWl[buf][woff] = l;                               \
        } else {                                                        \
            uint4 h;                                                    \
            cvt8(af0, af1, h);  *(uint4*)&sAh[buf][aoff] = h;           \
            cvt8(wf0, wf1, h);  *(uint4*)&sWh[buf][woff] = h;           \
        }                                                               \
    } while (0)

    GLOAD(0);
    GSTORE(0);
    __syncthreads();

    for (int kc = 0; kc < 16; kc++) {
        if (kc < 15) GLOAD(kc + 1);
        const int buf = kc & 1;

        const uint32_t aAddr0 = sptr(&sAh[buf][(wm * 32 + lrow) * AST + lcol]);
        const uint32_t bAddr0 = sptr(&sWh[buf][lrow * WST + wn * 64 + lcol]);

        uint32_t ah[2][4], bh[4][4];
#pragma unroll
        for (int mt = 0; mt < 2; mt++)
            ldsm4(ah[mt], aAddr0 + mt * (16 * AST * 2));
#pragma unroll
        for (int nb = 0; nb < 4; nb++)
            ldsm4t(bh[nb], bAddr0 + nb * 32);

#pragma unroll
        for (int mt = 0; mt < 2; mt++)
#pragma unroll
            for (int j = 0; j < 8; j++)
                mma16816(acc[mt][j], ah[mt], &bh[j >> 1][(j & 1) * 2]);

        if (SPLIT) {
            const uint32_t aAddrL = sptr(&sAl[buf][(wm * 32 + lrow) * AST + lcol]);
            const uint32_t bAddrL = sptr(&sWl[buf][lrow * WST + wn * 64 + lcol]);
            uint32_t al[2][4], bl[4][4];
#pragma unroll
            for (int mt = 0; mt < 2; mt++)
                ldsm4(al[mt], aAddrL + mt * (16 * AST * 2));
#pragma unroll
            for (int nb = 0; nb < 4; nb++)
                ldsm4t(bl[nb], bAddrL + nb * 32);

#pragma unroll
            for (int mt = 0; mt < 2; mt++)
#pragma unroll
                for (int j = 0; j < 8; j++) {
                    mma16816(acc[mt][j], ah[mt], &bl[j >> 1][(j & 1) * 2]);
                    mma16816(acc[mt][j], al[mt], &bh[j >> 1][(j & 1) * 2]);
                }
        }

        if (kc < 15) {
            GSTORE((kc + 1) & 1);
            __syncthreads();
        }
    }
#undef GLOAD
#undef GSTORE

#pragma unroll
    for (int mt = 0; mt < 2; mt++) {
        const int r0 = m0 + wm * 32 + mt * 16 + (lane >> 2);
#pragma unroll
        for (int j = 0; j < 8; j++) {
            const int c0 = n0 + wn * 64 + j * 8 + (lane & 3) * 2;
            const float2 bb = *(const float2*)&bias[c0];
            const float d0 = acc[mt][j][0] + bb.x;
            const float d1 = acc[mt][j][1] + bb.y;
            const float d2 = acc[mt][j][2] + bb.x;
            const float d3 = acc[mt][j][3] + bb.y;
            if (HALF_OUT) {
                __half* C = (__half*)Cout;
                *(__half2*)(C + (size_t)r0 * N + c0)       = __floats2half2_rn(d0, d1);
                *(__half2*)(C + (size_t)(r0 + 8) * N + c0) = __floats2half2_rn(d2, d3);
            } else {
                float* C = (float*)Cout;
                *(float2*)(C + (size_t)r0 * N + c0)       = make_float2(d0, d1);
                *(float2*)(C + (size_t)(r0 + 8) * N + c0) = make_float2(d2, d3);
            }
        }
    }
}

// ---------------------------------------------------------------------------
// Fused prep+gather: block per (b,q), warp per head.
// Phase 1: identical to R12-passing version (all 4 corner offsets clamped
//   individually in-bounds; weights zeroed where invalid -> exact zero-pad).
// Phase 2 (restructured): lanes split 4 ways over corners (cid = lane>>3);
//   each lane loads LDG.64 = 4 dims of its corner; 16 iterations total
//   (was 32 x LDG.32). Corner reduce via shfl_xor(8), shfl_xor(16);
//   lanes 0-7 store one float4 (coalesced 128 B/warp).
// ---------------------------------------------------------------------------
__global__ __launch_bounds__(256) void fused_gather(
    const float* __restrict__ attnraw, const float* __restrict__ off,
    const float* __restrict__ refp, float* __restrict__ outp)
{
    __shared__ int   s_o[HEADS][16][4];   // per-corner half-index into g_valh
    __shared__ float s_w[HEADS][16][4];   // per-corner attn-folded weights

    const int bq   = blockIdx.x;
    const int h    = threadIdx.x >> 5;
    const int lane = threadIdx.x & 31;
    const int sm   = lane & 15;
    const int b    = (bq >= LQN) ? 1 : 0;

    // ---- Phase 1 (identical to R12) ----
    {
        float a = attnraw[(size_t)bq * 128 + h * 16 + sm];
        float mx = a;
#pragma unroll
        for (int i = 8; i > 0; i >>= 1)
            mx = fmaxf(mx, __shfl_xor_sync(0xffffffffu, mx, i, 16));
        float e = __expf(a - mx);
        float s = e;
#pragma unroll
        for (int i = 8; i > 0; i >>= 1)
            s += __shfl_xor_sync(0xffffffffu, s, i, 16);
        const float aw = e / s;

        const int l  = sm >> 2;
        const int Wl = 128 >> l;
        const int St = (65536 - (65536 >> (2 * l))) / 3;  // 0,16384,20480,21504
        const int rowbase = b * LINN + St;

        const float rx = refp[(size_t)bq * 8 + l * 2 + 0];
        const float ry = refp[(size_t)bq * 8 + l * 2 + 1];
        const float ox = off[(size_t)bq * 256 + h * 32 + sm * 2 + 0];
        const float oy = off[(size_t)bq * 256 + h * 32 + sm * 2 + 1];

        const float x = (rx + ox) * (float)Wl - 0.5f;
        const float y = (ry + oy) * (float)Wl - 0.5f;
        const float xf = floorf(x), yf = floorf(y);
        const float wx = x - xf, wy = y - yf;
        const int ix = (int)xf, iy = (int)yf;

        const float w00 = (1.f - wx) * (1.f - wy) * aw;
        const float w10 = wx * (1.f - wy) * aw;
        const float w01 = (1.f - wx) * wy * aw;
        const float w11 = wx * wy * aw;

        const bool vx0 = (ix >= 0) && (ix < Wl);
        const bool vx1 = (ix + 1 >= 0) && (ix + 1 < Wl);
        const bool vy0 = (iy >= 0) && (iy < Wl);
        const bool vy1 = (iy + 1 >= 0) && (iy + 1 < Wl);

        const int x0c = min(max(ix, 0), Wl - 1);
        const int x1c = min(max(ix + 1, 0), Wl - 1);
        const int y0c = min(max(iy, 0), Wl - 1);
        const int y1c = min(max(iy + 1, 0), Wl - 1);

        if (lane < 16) {
            const int hb = h << 5;   // half-index of this head within a row
            s_o[h][sm][0] = ((rowbase + y0c * Wl + x0c) << 8) + hb;
            s_o[h][sm][1] = ((rowbase + y0c * Wl + x1c) << 8) + hb;
            s_o[h][sm][2] = ((rowbase + y1c * Wl + x0c) << 8) + hb;
            s_o[h][sm][3] = ((rowbase + y1c * Wl + x1c) << 8) + hb;
            s_w[h][sm][0] = (vx0 && vy0) ? w00 : 0.f;
            s_w[h][sm][1] = (vx1 && vy0) ? w10 : 0.f;
            s_w[h][sm][2] = (vx0 && vy1) ? w01 : 0.f;
            s_w[h][sm][3] = (vx1 && vy1) ? w11 : 0.f;
        }
    }
    __syncwarp();

    // ---- Phase 2 (4-corner lane split, LDG.64) ----
    const int cid = lane >> 3;            // corner 0..3
    const int dq  = (lane & 7) * 4;       // 4-dim group within the 32-dim head

    float a0 = 0.f, a1 = 0.f, a2 = 0.f, a3 = 0.f;
#pragma unroll
    for (int s = 0; s < 16; s++) {
        const int   o = s_o[h][s][cid];   // broadcast within 8-lane group
        const float w = s_w[h][s][cid];
        const uint2 v = *(const uint2*)(g_valh + o + dq);   // LDG.64: 4 dims
        const float2 f0 = __half22float2(*(const __half2*)&v.x);
        const float2 f1 = __half22float2(*(const __half2*)&v.y);
        a0 = fmaf(w, f0.x, a0);
        a1 = fmaf(w, f0.y, a1);
        a2 = fmaf(w, f1.x, a2);
        a3 = fmaf(w, f1.y, a3);
    }
    // sum the 4 corners: lanes L, L+8, L+16, L+24 hold the same dim group
    a0 += __shfl_xor_sync(0xffffffffu, a0, 8);
    a1 += __shfl_xor_sync(0xffffffffu, a1, 8);
    a2 += __shfl_xor_sync(0xffffffffu, a2, 8);
    a3 += __shfl_xor_sync(0xffffffffu, a3, 8);
    a0 += __shfl_xor_sync(0xffffffffu, a0, 16);
    a1 += __shfl_xor_sync(0xffffffffu, a1, 16);
    a2 += __shfl_xor_sync(0xffffffffu, a2, 16);
    a3 += __shfl_xor_sync(0xffffffffu, a3, 16);
    if (lane < 8)
        *(float4*)(outp + (size_t)bq * 256 + h * 32 + lane * 4) =
            make_float4(a0, a1, a2, a3);
}

// ---------------------------------------------------------------------------
// kernel_launch — graph-capturable, allocation-free, deterministic.
// Inputs: query, reference_points, input_flatten, spatial_shapes(i64, unused),
// level_start_index(i64, unused), Wv, bv, Woff, boff, Wa, ba, Wo, bo.
// ---------------------------------------------------------------------------
extern "C" void kernel_launch(void* const* d_in, const int* in_sizes, int n_in,
                              void* d_out, int out_size)
{
    const float* query = (const float*)d_in[0];
    const float* refp  = (const float*)d_in[1];
    const float* inpf  = (const float*)d_in[2];
    const float* Wv    = (const float*)d_in[5];
    const float* bv    = (const float*)d_in[6];
    const float* Woff  = (const float*)d_in[7];
    const float* boff  = (const float*)d_in[8];
    const float* Wa    = (const float*)d_in[9];
    const float* ba    = (const float*)d_in[10];
    const float* Wo    = (const float*)d_in[11];
    const float* bo    = (const float*)d_in[12];
    float* out = (float*)d_out;

    void *valp, *offp, *arawp, *aoutp;
    cudaGetSymbolAddress(&valp,  g_valh);
    cudaGetSymbolAddress(&offp,  g_off);
    cudaGetSymbolAddress(&arawp, g_attnraw);
    cudaGetSymbolAddress(&aoutp, g_attout);

    dim3 blk(256);
    dim3 g2(NROWS / 128, 2);   // N = 256
    dim3 g1(NROWS / 128, 1);   // N = 128

    // value (split-fp16, fp16 row-major out)
    gemm_hmma<true,  true ><<<g2, blk>>>(inpf,  Wv,   bv,   valp,  256);
    // sampling offsets (split-fp16 — coordinate-sensitive)
    gemm_hmma<true,  false><<<g2, blk>>>(query, Woff, boff, offp,  256);
    // attn logits (plain fp16 — softmax-insensitive)
    gemm_hmma<false, false><<<g1, blk>>>(query, Wa,   ba,   arawp, 128);

    fused_gather<<<NROWS, blk>>>((const float*)arawp, (const float*)offp,
                                 refp, (float*)aoutp);

    // output projection (split-fp16)
    gemm_hmma<true,  false><<<g2, blk>>>((const float*)aoutp, Wo, bo, out, 256);
}